// round 6
// baseline (speedup 1.0000x reference)
#include <cuda_runtime.h>
#include <cstdint>
#include <math.h>

#define N_NODES 25000
#define N_EDGES 400000
#define ROWS    50000
#define DIM     128
#define INV_DT  5.0f   // fp32(1/fp32(0.2)) == 5.0f; XLA fast-math does ts*5.0f

// ---------------- device scratch (static; no allocation) ----------------
__device__ float g_Xq[(size_t)N_NODES * DIM];
__device__ float g_Xk[(size_t)N_NODES * DIM];
__device__ float g_Xv[(size_t)N_NODES * DIM];
__device__ float g_Tk[(size_t)ROWS * DIM];
__device__ float g_Tv[(size_t)ROWS * DIM];
// W in mma fragment order: [mat 0..4][plane hi/lo][kstep 0..15][ntile 0..15][lane 0..31][j 0..1]
// mats: 0=WQ_top 1=WK_top 2=WV_top 3=WK_bot 4=WV_bot
#define WF_PER_MAT (2 * 16 * 16 * 32 * 2)   // 32768 floats per mat
__device__ float g_Wf[5 * WF_PER_MAT];
__device__ float g_s[N_NODES];
__device__ float g_qt[DIM];
__device__ int   g_is64;

// ---------------- helpers ----------------
__device__ __forceinline__ float tf32r(float v) {
    unsigned u;
    asm("cvt.rna.tf32.f32 %0, %1;" : "=r"(u) : "f"(v));
    return __uint_as_float(u);
}
__device__ __forceinline__ unsigned tf32u(float v) {
    unsigned u;
    asm("cvt.rna.tf32.f32 %0, %1;" : "=r"(u) : "f"(v));
    return u;
}
__device__ __forceinline__ int bucket(float tval) {
    int idx = (int)floorf(__fmul_rn(tval, INV_DT));
    return max(0, min(idx, ROWS - 1));
}

// m16n8k8 tf32 mma: D = A*B + D (fp32 accumulate)
__device__ __forceinline__ void mma_tf32(float* c, const unsigned* a,
                                         unsigned b0, unsigned b1) {
    asm volatile(
        "mma.sync.aligned.m16n8k8.row.col.f32.tf32.tf32.f32 "
        "{%0,%1,%2,%3}, {%4,%5,%6,%7}, {%8,%9}, {%0,%1,%2,%3};"
        : "+f"(c[0]), "+f"(c[1]), "+f"(c[2]), "+f"(c[3])
        : "r"(a[0]), "r"(a[1]), "r"(a[2]), "r"(a[3]), "r"(b0), "r"(b1));
}

// ---------------- small prep kernels ----------------
__global__ void detect_kernel(const int* __restrict__ ei) {
    int all0 = 1;
    for (int i = 0; i < 32; i++)
        if (ei[2 * i + 1] != 0) all0 = 0;
    g_is64 = all0;
}

// Build fragment-ordered, tf32 hi/lo split W.
// Fragment mapping (m16n8k8, B col-major): b_j for lane: k = s*8 + (lane&3) + 4*j,
// n = nt*8 + (lane>>2).
__global__ void wfrag_kernel(const float* __restrict__ WQ,
                             const float* __restrict__ WK,
                             const float* __restrict__ WV) {
    int idx = blockIdx.x * 256 + threadIdx.x;
    if (idx >= 5 * WF_PER_MAT) return;
    int j     = idx & 1;
    int lane  = (idx >> 1) & 31;
    int nt    = (idx >> 6) & 15;
    int s     = (idx >> 10) & 15;
    int plane = (idx >> 14) & 1;
    int mat   = idx >> 15;
    int k = s * 8 + (lane & 3) + 4 * j;
    int n = nt * 8 + (lane >> 2);
    const float* W = (mat == 0) ? WQ : (mat == 1 || mat == 3) ? WK : WV;
    int row = ((mat < 3) ? 0 : DIM) + k;
    float w = W[(size_t)row * DIM + n];
    float hi = tf32r(w);
    g_Wf[idx] = plane ? tf32r(w - hi) : hi;
}

__global__ void qt_kernel(const float* __restrict__ TE,
                          const float* __restrict__ WQ,
                          const float* __restrict__ t) {
    int idx = bucket(t[0]);
    const float* phi = TE + (size_t)idx * DIM;
    int o = threadIdx.x;
    float acc = 0.0f;
    #pragma unroll 8
    for (int k = 0; k < DIM; k++)
        acc += phi[k] * WQ[(size_t)(DIM + k) * DIM + o];
    g_qt[o] = acc;
}

__global__ void zero_s_kernel() {
    int i = blockIdx.x * 256 + threadIdx.x;
    if (i < N_NODES) g_s[i] = 0.0f;
}

// ---------------- 3xTF32 HMMA GEMM: C[M x 128] = A[M x 128] @ W ----------
// block = 128 threads (4 warps); warp tile = 16 rows x 128 cols.
// A fragments loaded straight from global (L2-resident), split hi/lo on the fly.
// B fragments from g_Wf (fragment order, L1-resident).
__global__ void __launch_bounds__(128)
gemm_hmma(const float* __restrict__ A, int M,
          const float* __restrict__ Wf,      // one mat: hi plane, +16384 = lo
          float* __restrict__ C,
          const float* __restrict__ bias) {
    int tid = threadIdx.x;
    int warp = tid >> 5;
    int lane = tid & 31;
    int gid = lane >> 2;      // groupID = row within octet
    int tig = lane & 3;       // thread-in-group = k offset

    int rb = blockIdx.x * 64 + warp * 16;
    int r0 = rb + gid;
    int r1 = r0 + 8;
    bool v0 = r0 < M, v1 = r1 < M;

    float acc[16][4];
    #pragma unroll
    for (int nt = 0; nt < 16; nt++)
        #pragma unroll
        for (int q = 0; q < 4; q++) acc[nt][q] = 0.0f;

    const float* a0p = A + (size_t)r0 * DIM + tig;
    const float* a1p = A + (size_t)r1 * DIM + tig;

    #pragma unroll 1
    for (int s = 0; s < 16; s++) {
        // A fragment: a0=(r0,k) a1=(r1,k) a2=(r0,k+4) a3=(r1,k+4), k = s*8+tig
        float f0 = v0 ? __ldg(a0p + s * 8)     : 0.0f;
        float f1 = v1 ? __ldg(a1p + s * 8)     : 0.0f;
        float f2 = v0 ? __ldg(a0p + s * 8 + 4) : 0.0f;
        float f3 = v1 ? __ldg(a1p + s * 8 + 4) : 0.0f;
        unsigned ahi[4], alo[4];
        ahi[0] = tf32u(f0); alo[0] = tf32u(f0 - __uint_as_float(ahi[0]));
        ahi[1] = tf32u(f1); alo[1] = tf32u(f1 - __uint_as_float(ahi[1]));
        ahi[2] = tf32u(f2); alo[2] = tf32u(f2 - __uint_as_float(ahi[2]));
        ahi[3] = tf32u(f3); alo[3] = tf32u(f3 - __uint_as_float(ahi[3]));

        const uint2* bh = (const uint2*)(Wf)         + (s * 16) * 32 + lane;
        const uint2* bl = (const uint2*)(Wf + 16384) + (s * 16) * 32 + lane;
        #pragma unroll
        for (int nt = 0; nt < 16; nt++) {
            uint2 bhv = __ldg(bh + nt * 32);
            uint2 blv = __ldg(bl + nt * 32);
            mma_tf32(acc[nt], ahi, bhv.x, bhv.y);   // hi * hi
            mma_tf32(acc[nt], ahi, blv.x, blv.y);   // hi * lo
            mma_tf32(acc[nt], alo, bhv.x, bhv.y);   // lo * hi
        }
    }

    // epilogue: c0,c1 -> (r0, col..col+1) ; c2,c3 -> (r1, ...)
    #pragma unroll
    for (int nt = 0; nt < 16; nt++) {
        int col = nt * 8 + 2 * tig;
        float b0 = 0.f, b1 = 0.f;
        if (bias) { b0 = bias[col]; b1 = bias[col + 1]; }
        if (v0) {
            float2 o = make_float2(acc[nt][0] + b0, acc[nt][1] + b1);
            *(float2*)(C + (size_t)r0 * DIM + col) = o;
        }
        if (v1) {
            float2 o = make_float2(acc[nt][2] + b0, acc[nt][3] + b1);
            *(float2*)(C + (size_t)r1 * DIM + col) = o;
        }
    }
}

// ---------------- fused edge pass: one warp per edge ----------------
__global__ void __launch_bounds__(256) edge_kernel(const void* __restrict__ ei_raw,
                                                   const float* __restrict__ ts,
                                                   float* __restrict__ out) {
    int gw = (blockIdx.x * 256 + threadIdx.x) >> 5;
    int lane = threadIdx.x & 31;
    if (gw >= N_EDGES) return;

    int src, dst;
    if (g_is64) {
        const long long* p = (const long long*)ei_raw;
        src = (int)p[gw];
        dst = (int)p[N_EDGES + gw];
    } else {
        const int* p = (const int*)ei_raw;
        src = p[gw];
        dst = p[N_EDGES + gw];
    }
    int idx = bucket(__ldg(ts + gw));

    const float4* q4  = (const float4*)g_Xq + (size_t)dst * 32;
    const float4* k4  = (const float4*)g_Xk + (size_t)src * 32;
    const float4* tk4 = (const float4*)g_Tk + (size_t)idx * 32;

    float4 q  = q4[lane];
    float4 k  = k4[lane];
    float4 tk = tk4[lane];
    float part = q.x * (k.x + tk.x) + q.y * (k.y + tk.y) +
                 q.z * (k.z + tk.z) + q.w * (k.w + tk.w);
    #pragma unroll
    for (int off = 16; off; off >>= 1)
        part += __shfl_xor_sync(0xffffffffu, part, off);

    float w = expf(part);   // segment max skipped: |alpha| << 88, s >= 1

    const float4* v4  = (const float4*)g_Xv + (size_t)src * 32;
    const float4* tv4 = (const float4*)g_Tv + (size_t)idx * 32;
    float4 v  = v4[lane];
    float4 tv = tv4[lane];
    float4 r = make_float4(w * (v.x + tv.x), w * (v.y + tv.y),
                           w * (v.z + tv.z), w * (v.w + tv.w));

    atomicAdd(((float4*)(out + (size_t)dst * DIM)) + lane, r);
    if (lane == 0)
        atomicAdd(g_s + dst, w);
}

__global__ void norm_kernel(float* __restrict__ out) {
    int i = blockIdx.x * 256 + threadIdx.x;
    if (i < N_NODES * DIM)
        out[i] = out[i] / (g_s[i >> 7] + 1e-16f);
}

// ---------------- launch ----------------
extern "C" void kernel_launch(void* const* d_in, const int* in_sizes, int n_in,
                              void* d_out, int out_size) {
    const float* x  = (const float*)d_in[0];
    const void*  ei = d_in[1];
    const float* ts = (const float*)d_in[2];
    const float* t  = (const float*)d_in[3];
    const float* TE = (const float*)d_in[4];
    const float* WQ = (const float*)d_in[5];
    const float* WK = (const float*)d_in[6];
    const float* WV = (const float*)d_in[7];
    float* out = (float*)d_out;

    float *Xq, *Xk, *Xv, *Tk, *Tv, *qt, *Wf;
    cudaGetSymbolAddress((void**)&Xq, g_Xq);
    cudaGetSymbolAddress((void**)&Xk, g_Xk);
    cudaGetSymbolAddress((void**)&Xv, g_Xv);
    cudaGetSymbolAddress((void**)&Tk, g_Tk);
    cudaGetSymbolAddress((void**)&Tv, g_Tv);
    cudaGetSymbolAddress((void**)&qt, g_qt);
    cudaGetSymbolAddress((void**)&Wf, g_Wf);

    detect_kernel<<<1, 1>>>((const int*)ei);
    wfrag_kernel<<<(5 * WF_PER_MAT + 255) / 256, 256>>>(WQ, WK, WV);
    qt_kernel<<<1, DIM>>>(TE, WQ, t);
    zero_s_kernel<<<(N_NODES + 255) / 256, 256>>>();
    cudaMemsetAsync(d_out, 0, (size_t)N_NODES * DIM * sizeof(float));

    int nb_node  = (N_NODES + 63) / 64;
    int nb_table = (ROWS + 63) / 64;
    gemm_hmma<<<nb_node, 128>>>(x, N_NODES, Wf + 0 * WF_PER_MAT, Xq, qt);
    gemm_hmma<<<nb_node, 128>>>(x, N_NODES, Wf + 1 * WF_PER_MAT, Xk, nullptr);
    gemm_hmma<<<nb_node, 128>>>(x, N_NODES, Wf + 2 * WF_PER_MAT, Xv, nullptr);
    gemm_hmma<<<nb_table, 128>>>(TE, ROWS, Wf + 3 * WF_PER_MAT, Tk, nullptr);
    gemm_hmma<<<nb_table, 128>>>(TE, ROWS, Wf + 4 * WF_PER_MAT, Tv, nullptr);

    edge_kernel<<<(N_EDGES * 32 + 255) / 256, 256>>>(ei, ts, out);
    norm_kernel<<<(N_NODES * DIM + 255) / 256, 256>>>(out);
}

// round 7
// speedup vs baseline: 1.2658x; 1.2658x over previous
#include <cuda_runtime.h>
#include <cstdint>
#include <math.h>

#define N_NODES 25000
#define N_EDGES 400000
#define ROWS    50000
#define DIM     128
#define INV_DT  5.0f   // fp32(1/fp32(0.2)) == 5.0f; XLA fast-math does ts*5.0f

typedef unsigned long long ull;

// ---------------- device scratch (static; no allocation) ----------------
__device__ float g_Xq[(size_t)N_NODES * DIM];
__device__ float g_Xk[(size_t)N_NODES * DIM];
__device__ float g_Xv[(size_t)N_NODES * DIM];
__device__ float g_Tk[(size_t)ROWS * DIM];
__device__ float g_Tv[(size_t)ROWS * DIM];
// k-pair packed weights: [mat 0..4][kpair 0..63][col 0..127] ull = (W[2kp][c], W[2kp+1][c])
// mats: 0=WQ_top 1=WK_top 2=WV_top 3=WK_bot 4=WV_bot
__device__ ull g_Wp[5 * 64 * DIM];
__device__ float g_s[N_NODES];
__device__ float g_qt[DIM];
__device__ int   g_is64;

// ---------------- helpers ----------------
union U64F2 { ull u; float2 f; };

__device__ __forceinline__ ull fma2(ull a, ull b, ull c) {
    ull d;
    asm("fma.rn.f32x2 %0, %1, %2, %3;" : "=l"(d) : "l"(a), "l"(b), "l"(c));
    return d;
}

__device__ __forceinline__ int bucket(float tval) {
    int idx = (int)floorf(__fmul_rn(tval, INV_DT));
    return max(0, min(idx, ROWS - 1));
}

// ---------------- small prep kernels ----------------
__global__ void detect_kernel(const int* __restrict__ ei) {
    int all0 = 1;
    for (int i = 0; i < 32; i++)
        if (ei[2 * i + 1] != 0) all0 = 0;
    g_is64 = all0;
}

__global__ void wpack_kernel(const float* __restrict__ WQ,
                             const float* __restrict__ WK,
                             const float* __restrict__ WV) {
    int idx = blockIdx.x * 256 + threadIdx.x;
    if (idx >= 5 * 64 * DIM) return;
    int m = idx >> 13;          // /8192
    int rem = idx & 8191;
    int kp = rem >> 7;
    int c = rem & 127;
    const float* W = (m == 0) ? WQ : (m == 1 || m == 3) ? WK : WV;
    int row = ((m < 3) ? 0 : DIM) + 2 * kp;
    U64F2 u;
    u.f.x = W[(size_t)row * DIM + c];
    u.f.y = W[(size_t)(row + 1) * DIM + c];
    g_Wp[idx] = u.u;
}

__global__ void qt_kernel(const float* __restrict__ TE,
                          const float* __restrict__ WQ,
                          const float* __restrict__ t) {
    int idx = bucket(t[0]);
    const float* phi = TE + (size_t)idx * DIM;
    int o = threadIdx.x;
    float acc = 0.0f;
    #pragma unroll 8
    for (int k = 0; k < DIM; k++)
        acc += phi[k] * WQ[(size_t)(DIM + k) * DIM + o];
    g_qt[o] = acc;
}

// ---------------- W-stationary f32x2 GEMM ------------------------------
// C[M x 128] = A[M x 128] @ W[128 x 128] (+bias broadcast over rows).
// block = 256 threads (8 warps); tile = 64 rows; W staged whole in SMEM.
// thread: cg = tid&31 -> cols {cg, cg+32, cg+64, cg+96}; warp w -> rows 8w..8w+7.
// K packed in pairs into f32x2 lanes; lanes summed in epilogue.
__global__ void __launch_bounds__(256)
gemm_sw(const float* __restrict__ A, int M,
        const ull* __restrict__ Wp,        // one mat: 64 x 128 ull
        float* __restrict__ C,
        const float* __restrict__ bias) {
    extern __shared__ ull Ws[];            // 8192 ull = 64 KB
    int tid = threadIdx.x;
    int cg = tid & 31;
    int wid = tid >> 5;

    // stage W (coalesced, 16B vectors)
    {
        const ulonglong2* src = (const ulonglong2*)Wp;
        ulonglong2* dst = (ulonglong2*)Ws;
        #pragma unroll
        for (int i = 0; i < 16; i++)
            dst[tid + i * 256] = src[tid + i * 256];
    }
    __syncthreads();

    int r0 = blockIdx.x * 64 + wid * 8;

    ull acc[8][4];
    #pragma unroll
    for (int r = 0; r < 8; r++)
        #pragma unroll
        for (int j = 0; j < 4; j++) acc[r][j] = 0ull;

    #pragma unroll 1
    for (int kc = 0; kc < 32; kc++) {      // 4 k per chunk = 2 kpairs
        ulonglong2 a2[8];                  // (k0,k1),(k2,k3) per row
        #pragma unroll
        for (int r = 0; r < 8; r++) {
            int row = r0 + r;
            if (row < M)
                a2[r] = *(const ulonglong2*)(A + (size_t)row * DIM + kc * 4);
            else
                a2[r] = make_ulonglong2(0ull, 0ull);
        }
        #pragma unroll
        for (int kp = 0; kp < 2; kp++) {
            ull w[4];
            const ull* wrow = Ws + (kc * 2 + kp) * DIM + cg;
            #pragma unroll
            for (int j = 0; j < 4; j++) w[j] = wrow[j * 32];
            #pragma unroll
            for (int r = 0; r < 8; r++) {
                ull a = kp ? a2[r].y : a2[r].x;
                #pragma unroll
                for (int j = 0; j < 4; j++)
                    acc[r][j] = fma2(a, w[j], acc[r][j]);
            }
        }
    }

    float b[4] = {0.f, 0.f, 0.f, 0.f};
    if (bias) {
        #pragma unroll
        for (int j = 0; j < 4; j++) b[j] = bias[cg + 32 * j];
    }
    #pragma unroll
    for (int r = 0; r < 8; r++) {
        int row = r0 + r;
        if (row < M) {
            float* dst = C + (size_t)row * DIM + cg;
            #pragma unroll
            for (int j = 0; j < 4; j++) {
                U64F2 u; u.u = acc[r][j];
                dst[j * 32] = u.f.x + u.f.y + b[j];
            }
        }
    }
}

// ---------------- fused edge pass: one warp per edge ----------------
__global__ void __launch_bounds__(256) edge_kernel(const void* __restrict__ ei_raw,
                                                   const float* __restrict__ ts,
                                                   float* __restrict__ out) {
    int gw = (blockIdx.x * 256 + threadIdx.x) >> 5;
    int lane = threadIdx.x & 31;
    if (gw >= N_EDGES) return;

    int src, dst;
    if (g_is64) {
        const long long* p = (const long long*)ei_raw;
        src = (int)p[gw];
        dst = (int)p[N_EDGES + gw];
    } else {
        const int* p = (const int*)ei_raw;
        src = p[gw];
        dst = p[N_EDGES + gw];
    }
    int idx = bucket(__ldg(ts + gw));

    const float4* q4  = (const float4*)g_Xq + (size_t)dst * 32;
    const float4* k4  = (const float4*)g_Xk + (size_t)src * 32;
    const float4* tk4 = (const float4*)g_Tk + (size_t)idx * 32;

    float4 q  = q4[lane];
    float4 k  = k4[lane];
    float4 tk = tk4[lane];
    float part = q.x * (k.x + tk.x) + q.y * (k.y + tk.y) +
                 q.z * (k.z + tk.z) + q.w * (k.w + tk.w);
    #pragma unroll
    for (int off = 16; off; off >>= 1)
        part += __shfl_xor_sync(0xffffffffu, part, off);

    float w = expf(part);   // segment max skipped: |alpha| << 88, s >= 1

    const float4* v4  = (const float4*)g_Xv + (size_t)src * 32;
    const float4* tv4 = (const float4*)g_Tv + (size_t)idx * 32;
    float4 v  = v4[lane];
    float4 tv = tv4[lane];
    float4 r = make_float4(w * (v.x + tv.x), w * (v.y + tv.y),
                           w * (v.z + tv.z), w * (v.w + tv.w));

    atomicAdd(((float4*)(out + (size_t)dst * DIM)) + lane, r);
    if (lane == 0)
        atomicAdd(g_s + dst, w);
}

__global__ void norm_kernel(float* __restrict__ out) {
    int i = blockIdx.x * 256 + threadIdx.x;
    if (i < N_NODES * DIM)
        out[i] = out[i] / (g_s[i >> 7] + 1e-16f);
}

// ---------------- launch ----------------
extern "C" void kernel_launch(void* const* d_in, const int* in_sizes, int n_in,
                              void* d_out, int out_size) {
    const float* x  = (const float*)d_in[0];
    const void*  ei = d_in[1];
    const float* ts = (const float*)d_in[2];
    const float* t  = (const float*)d_in[3];
    const float* TE = (const float*)d_in[4];
    const float* WQ = (const float*)d_in[5];
    const float* WK = (const float*)d_in[6];
    const float* WV = (const float*)d_in[7];
    float* out = (float*)d_out;

    float *Xq, *Xk, *Xv, *Tk, *Tv, *qt, *s;
    ull* Wp;
    cudaGetSymbolAddress((void**)&Xq, g_Xq);
    cudaGetSymbolAddress((void**)&Xk, g_Xk);
    cudaGetSymbolAddress((void**)&Xv, g_Xv);
    cudaGetSymbolAddress((void**)&Tk, g_Tk);
    cudaGetSymbolAddress((void**)&Tv, g_Tv);
    cudaGetSymbolAddress((void**)&qt, g_qt);
    cudaGetSymbolAddress((void**)&s,  g_s);
    cudaGetSymbolAddress((void**)&Wp, g_Wp);

    const int SMEM = 64 * 1024;
    cudaFuncSetAttribute(gemm_sw, cudaFuncAttributeMaxDynamicSharedMemorySize, SMEM);

    detect_kernel<<<1, 1>>>((const int*)ei);
    wpack_kernel<<<(5 * 64 * DIM + 255) / 256, 256>>>(WQ, WK, WV);
    qt_kernel<<<1, DIM>>>(TE, WQ, t);
    cudaMemsetAsync(s, 0, N_NODES * sizeof(float));
    cudaMemsetAsync(d_out, 0, (size_t)N_NODES * DIM * sizeof(float));

    int nb_node  = (N_NODES + 63) / 64;
    int nb_table = (ROWS + 63) / 64;
    gemm_sw<<<nb_node, 256, SMEM>>>(x, N_NODES, Wp + 0 * 8192, Xq, qt);
    gemm_sw<<<nb_node, 256, SMEM>>>(x, N_NODES, Wp + 1 * 8192, Xk, nullptr);
    gemm_sw<<<nb_node, 256, SMEM>>>(x, N_NODES, Wp + 2 * 8192, Xv, nullptr);
    gemm_sw<<<nb_table, 256, SMEM>>>(TE, ROWS, Wp + 3 * 8192, Tk, nullptr);
    gemm_sw<<<nb_table, 256, SMEM>>>(TE, ROWS, Wp + 4 * 8192, Tv, nullptr);

    edge_kernel<<<(N_EDGES * 32 + 255) / 256, 256>>>(ei, ts, out);
    norm_kernel<<<(N_NODES * DIM + 255) / 256, 256>>>(out);
}

// round 8
// speedup vs baseline: 1.6245x; 1.2834x over previous
#include <cuda_runtime.h>
#include <cstdint>
#include <math.h>

#define N_NODES 25000
#define N_EDGES 400000
#define ROWS    50000
#define DIM     128
#define INV_DT  5.0f   // fp32(1/fp32(0.2)) == 5.0f; XLA fast-math does ts*5.0f

typedef unsigned long long ull;

#define NB_NODE  391   // (25000+63)/64
#define NB_TABLE 782   // (50000+63)/64
#define GRID_GEMM (3 * NB_NODE + 2 * NB_TABLE)   // 2737

// ---------------- device scratch (static; no allocation) ----------------
__device__ float g_Xq[(size_t)N_NODES * DIM];
__device__ float g_Xk[(size_t)N_NODES * DIM];
__device__ float g_Xv[(size_t)N_NODES * DIM];
__device__ float g_Tk[(size_t)ROWS * DIM];
__device__ float g_Tv[(size_t)ROWS * DIM];
// k-pair packed weights: [mat 0..4][kpair 0..63][col 0..127] ull = (W[2kp][c], W[2kp+1][c])
// mats: 0=WQ_top 1=WK_top 2=WV_top 3=WK_bot 4=WV_bot
__device__ ull g_Wp[5 * 64 * DIM];
__device__ float g_s[N_NODES];
__device__ float g_qt[DIM];
__device__ int   g_is64;

// ---------------- helpers ----------------
union U64F2 { ull u; float2 f; };

__device__ __forceinline__ ull fma2(ull a, ull b, ull c) {
    ull d;
    asm("fma.rn.f32x2 %0, %1, %2, %3;" : "=l"(d) : "l"(a), "l"(b), "l"(c));
    return d;
}

__device__ __forceinline__ int bucket(float tval) {
    int idx = (int)floorf(__fmul_rn(tval, INV_DT));
    return max(0, min(idx, ROWS - 1));
}

// ---------------- fused prep: wpack + detect + qt ----------------
// blocks 0..159: pack W ; block 160: dtype detect ; block 161: qt
__global__ void prep_kernel(const float* __restrict__ WQ,
                            const float* __restrict__ WK,
                            const float* __restrict__ WV,
                            const int* __restrict__ ei,
                            const float* __restrict__ TE,
                            const float* __restrict__ t) {
    int b = blockIdx.x;
    if (b < 160) {
        int idx = b * 256 + threadIdx.x;
        if (idx < 5 * 64 * DIM) {
            int m = idx >> 13;
            int rem = idx & 8191;
            int kp = rem >> 7;
            int c = rem & 127;
            const float* W = (m == 0) ? WQ : (m == 1 || m == 3) ? WK : WV;
            int row = ((m < 3) ? 0 : DIM) + 2 * kp;
            U64F2 u;
            u.f.x = W[(size_t)row * DIM + c];
            u.f.y = W[(size_t)(row + 1) * DIM + c];
            g_Wp[idx] = u.u;
        }
    } else if (b == 160) {
        if (threadIdx.x == 0) {
            int all0 = 1;
            for (int i = 0; i < 32; i++)
                if (ei[2 * i + 1] != 0) all0 = 0;
            g_is64 = all0;
        }
    } else {
        // qt = phi(t) @ WQ_bot
        int o = threadIdx.x;
        if (o < DIM) {
            int idx = bucket(t[0]);
            const float* phi = TE + (size_t)idx * DIM;
            float acc = 0.0f;
            #pragma unroll 8
            for (int k = 0; k < DIM; k++)
                acc += phi[k] * WQ[(size_t)(DIM + k) * DIM + o];
            g_qt[o] = acc;
        }
    }
}

// ---------------- one-launch 5-matrix GEMM ------------------------------
// C_m[M x 128] = A[M x 128] @ W_m[128 x 128] (+bias on mat 0).
// block = 256 threads (8 warps); tile = 64 rows; W (64KB) and A-tile (32KB)
// both staged in SMEM -> mainloop is pure LDS + FFMA2.
// thread: cg = tid&31 -> cols {cg, cg+32, cg+64, cg+96}; warp w -> rows 8w..8w+7.
__global__ void __launch_bounds__(256, 2)
gemm_all(const float* __restrict__ x, const float* __restrict__ TE) {
    extern __shared__ ull Ws[];                     // [8192] ull = 64 KB
    float* As = (float*)(Ws + 8192);                // [64][128] = 32 KB

    int bid = blockIdx.x;
    const float* A;
    int M, tile;
    const ull* Wp;
    float* C;
    bool with_bias = false;
    if (bid < 3 * NB_NODE) {
        int mat = bid / NB_NODE;
        tile = bid - mat * NB_NODE;
        A = x; M = N_NODES;
        Wp = g_Wp + mat * 8192;
        C = (mat == 0) ? g_Xq : (mat == 1) ? g_Xk : g_Xv;
        with_bias = (mat == 0);
    } else {
        int rem = bid - 3 * NB_NODE;
        int mat = rem / NB_TABLE;
        tile = rem - mat * NB_TABLE;
        A = TE; M = ROWS;
        Wp = g_Wp + (3 + mat) * 8192;
        C = mat ? g_Tv : g_Tk;
    }

    int tid = threadIdx.x;
    int cg = tid & 31;
    int wid = tid >> 5;
    int rb = tile * 64;

    // stage W (64KB, coalesced 16B)
    {
        const ulonglong2* src = (const ulonglong2*)Wp;
        ulonglong2* dst = (ulonglong2*)Ws;
        #pragma unroll
        for (int i = 0; i < 16; i++)
            dst[tid + i * 256] = src[tid + i * 256];
    }
    // stage A tile (64 x 128 floats, float4-coalesced)
    #pragma unroll
    for (int i = 0; i < 8; i++) {
        int q = tid + i * 256;          // 0..2047
        int r = q >> 5, c4 = q & 31;
        int row = rb + r;
        float4 v = (row < M) ? ((const float4*)A)[(size_t)row * 32 + c4]
                             : make_float4(0.f, 0.f, 0.f, 0.f);
        *(float4*)&As[r * 128 + c4 * 4] = v;
    }
    __syncthreads();

    const float* Arow = As + wid * 8 * 128;

    ull acc[8][4];
    #pragma unroll
    for (int r = 0; r < 8; r++)
        #pragma unroll
        for (int j = 0; j < 4; j++) acc[r][j] = 0ull;

    #pragma unroll 2
    for (int kc = 0; kc < 32; kc++) {      // 4 k per chunk = 2 kpairs
        ulonglong2 a2[8];                  // (k0,k1),(k2,k3) per row (LDS.128 bcast)
        #pragma unroll
        for (int r = 0; r < 8; r++)
            a2[r] = *(const ulonglong2*)&Arow[r * 128 + kc * 4];
        #pragma unroll
        for (int kp = 0; kp < 2; kp++) {
            ull w[4];
            const ull* wrow = Ws + (kc * 2 + kp) * DIM + cg;
            #pragma unroll
            for (int j = 0; j < 4; j++) w[j] = wrow[j * 32];
            #pragma unroll
            for (int r = 0; r < 8; r++) {
                ull a = kp ? a2[r].y : a2[r].x;
                #pragma unroll
                for (int j = 0; j < 4; j++)
                    acc[r][j] = fma2(a, w[j], acc[r][j]);
            }
        }
    }

    float b[4] = {0.f, 0.f, 0.f, 0.f};
    if (with_bias) {
        #pragma unroll
        for (int j = 0; j < 4; j++) b[j] = g_qt[cg + 32 * j];
    }
    int r0 = rb + wid * 8;
    #pragma unroll
    for (int r = 0; r < 8; r++) {
        int row = r0 + r;
        if (row < M) {
            float* dst = C + (size_t)row * DIM + cg;
            #pragma unroll
            for (int j = 0; j < 4; j++) {
                U64F2 u; u.u = acc[r][j];
                dst[j * 32] = u.f.x + u.f.y + b[j];
            }
        }
    }
}

// ---------------- fused edge pass: one warp per edge ----------------
__global__ void __launch_bounds__(256) edge_kernel(const void* __restrict__ ei_raw,
                                                   const float* __restrict__ ts,
                                                   float* __restrict__ out) {
    int gw = (blockIdx.x * 256 + threadIdx.x) >> 5;
    int lane = threadIdx.x & 31;
    if (gw >= N_EDGES) return;

    int src, dst;
    if (g_is64) {
        const long long* p = (const long long*)ei_raw;
        src = (int)p[gw];
        dst = (int)p[N_EDGES + gw];
    } else {
        const int* p = (const int*)ei_raw;
        src = p[gw];
        dst = p[N_EDGES + gw];
    }
    int idx = bucket(__ldg(ts + gw));

    const float4* q4  = (const float4*)g_Xq + (size_t)dst * 32;
    const float4* k4  = (const float4*)g_Xk + (size_t)src * 32;
    const float4* tk4 = (const float4*)g_Tk + (size_t)idx * 32;

    float4 q  = q4[lane];
    float4 k  = k4[lane];
    float4 tk = tk4[lane];
    float part = q.x * (k.x + tk.x) + q.y * (k.y + tk.y) +
                 q.z * (k.z + tk.z) + q.w * (k.w + tk.w);
    #pragma unroll
    for (int off = 16; off; off >>= 1)
        part += __shfl_xor_sync(0xffffffffu, part, off);

    float w = expf(part);   // segment max skipped: |alpha| << 88, s >= 1

    const float4* v4  = (const float4*)g_Xv + (size_t)src * 32;
    const float4* tv4 = (const float4*)g_Tv + (size_t)idx * 32;
    float4 v  = v4[lane];
    float4 tv = tv4[lane];
    float4 r = make_float4(w * (v.x + tv.x), w * (v.y + tv.y),
                           w * (v.z + tv.z), w * (v.w + tv.w));

    atomicAdd(((float4*)(out + (size_t)dst * DIM)) + lane, r);
    if (lane == 0)
        atomicAdd(g_s + dst, w);
}

__global__ void norm_kernel(float* __restrict__ out) {
    int i = blockIdx.x * 256 + threadIdx.x;
    if (i < N_NODES * DIM)
        out[i] = out[i] / (g_s[i >> 7] + 1e-16f);
}

// ---------------- launch ----------------
extern "C" void kernel_launch(void* const* d_in, const int* in_sizes, int n_in,
                              void* d_out, int out_size) {
    const float* x  = (const float*)d_in[0];
    const void*  ei = d_in[1];
    const float* ts = (const float*)d_in[2];
    const float* t  = (const float*)d_in[3];
    const float* TE = (const float*)d_in[4];
    const float* WQ = (const float*)d_in[5];
    const float* WK = (const float*)d_in[6];
    const float* WV = (const float*)d_in[7];
    float* out = (float*)d_out;

    float* s;
    cudaGetSymbolAddress((void**)&s, g_s);

    const int SMEM = 96 * 1024 + 1024;
    cudaFuncSetAttribute(gemm_all, cudaFuncAttributeMaxDynamicSharedMemorySize, SMEM);

    prep_kernel<<<162, 256>>>(WQ, WK, WV, (const int*)ei, TE, t);
    cudaMemsetAsync(s, 0, N_NODES * sizeof(float));
    cudaMemsetAsync(d_out, 0, (size_t)N_NODES * DIM * sizeof(float));

    gemm_all<<<GRID_GEMM, 256, SMEM>>>(x, TE);

    edge_kernel<<<(N_EDGES * 32 + 255) / 256, 256>>>(ei, ts, out);
    norm_kernel<<<(N_NODES * DIM + 255) / 256, 256>>>(out);
}